// round 4
// baseline (speedup 1.0000x reference)
#include <cuda_runtime.h>
#include <math.h>

#define Lc 8
#define Pc 8
#define Sc 128
#define Bc 16
#define Wc 768
#define Mc 64
#define W4   (Wc / 4)            // 192 float4 per W row
#define ROW4 ((Bc * Wc) / 4)     // s-stride in float4 = 3072
#define NBLK (Lc * Pc * Bc)      // 1024
#define NTHR 192

// Scratch (allocation-free: __device__ globals)
__device__ float g_mp[Lc * Pc * Bc * Wc];   // [l,p,b,w] max over s (3 MB)
__device__ float g_score[Lc * Pc * Bc];     // raw score per (l,p,b)
__device__ float g_sem[Lc * Bc * Wc];       // [l,b,w] (384 KB)

// Per-group barrier state: one 128B line per group [cnt, gen, pad...]
// A: 128 groups of 8 CTAs (key l*16+b).  B: 16 groups of 64 CTAs (key b).
__device__ unsigned g_barA[128 * 32];
__device__ unsigned g_barB[16 * 32];

// Generation-counting group barrier (reusable across graph replays).
// Called by thread 0 only; caller wraps with __syncthreads().
__device__ __forceinline__ void group_barrier(unsigned* line, unsigned size)
{
    volatile unsigned* cnt = line;
    volatile unsigned* gen = line + 1;
    __threadfence();                         // publish our pre-barrier stores
    unsigned g = *gen;                       // read BEFORE arriving
    if (atomicAdd((unsigned*)line, 1u) == size - 1) {
        *cnt = 0;
        __threadfence();
        atomicAdd((unsigned*)(line + 1), 1u);   // release
    } else {
        while (*gen == g) __nanosleep(32);
    }
    __threadfence();                         // acquire
}

// ---------------------------------------------------------------------------
// One fused persistent kernel: 1024 blocks x 192 threads, single wave.
// CTA id lpb = (l*8+p)*16+b.
// ---------------------------------------------------------------------------
__global__ __launch_bounds__(NTHR, 7)
void fused_kernel(const float* __restrict__ embeds,
                  const float* __restrict__ mask,
                  const float* __restrict__ w0,
                  const float* __restrict__ b0,
                  const float* __restrict__ w1,
                  const float* __restrict__ b1,
                  float* __restrict__ out)
{
    __shared__ float sw1[Sc];
    __shared__ float sred[6];
    __shared__ float s_bias;

    const int t   = threadIdx.x;             // 0..191
    const int lpb = blockIdx.x;
    const int b   = lpb & (Bc - 1);
    const int lp  = lpb >> 4;                 // l*8 + p
    const int p   = lp & 7;
    const int l   = lp >> 3;

    if (t < Sc) sw1[t] = __ldg(w1 + t);
    __syncthreads();
    if (t == 0) {
        float s = 0.0f;
        #pragma unroll 8
        for (int i = 0; i < Sc; i++) s += sw1[i];
        s_bias = b0[0] * s + b1[0];
    }

    // ===================== Phase 1: stream embeds (402 MB) =================
    {
        const float4* base = reinterpret_cast<const float4*>(embeds)
                           + (size_t)lp * Sc * ROW4 + (size_t)b * W4 + t;
        const float4 w0v = __ldg(reinterpret_cast<const float4*>(w0) + t);

        float4 mx = make_float4(-3.4e38f, -3.4e38f, -3.4e38f, -3.4e38f);
        float dot0 = 0.0f, dot1 = 0.0f;

        #pragma unroll 8
        for (int s = 0; s < Sc; s += 2) {
            float4 v0 = __ldcs(base + (size_t)s * ROW4);
            float4 v1 = __ldcs(base + (size_t)(s + 1) * ROW4);
            mx.x = fmaxf(mx.x, fmaxf(v0.x, v1.x));
            mx.y = fmaxf(mx.y, fmaxf(v0.y, v1.y));
            mx.z = fmaxf(mx.z, fmaxf(v0.z, v1.z));
            mx.w = fmaxf(mx.w, fmaxf(v0.w, v1.w));
            dot0 += (v0.x * w0v.x + v0.y * w0v.y + v0.z * w0v.z + v0.w * w0v.w) * sw1[s];
            dot1 += (v1.x * w0v.x + v1.y * w0v.y + v1.z * w0v.z + v1.w * w0v.w) * sw1[s + 1];
        }

        // L2-visible store (read by sibling CTAs in phase 2)
        __stcg(reinterpret_cast<float4*>(g_mp) + (size_t)lpb * W4 + t, mx);

        float dot = dot0 + dot1;
        #pragma unroll
        for (int o = 16; o > 0; o >>= 1)
            dot += __shfl_down_sync(0xffffffffu, dot, o);
        if ((t & 31) == 0) sred[t >> 5] = dot;
        __syncthreads();
        if (t == 0) {
            float sc = sred[0] + sred[1] + sred[2] + sred[3] + sred[4] + sred[5];
            __stcg(g_score + lpb, sc);
        }
    }

    // ========== Barrier A: sync the 8 CTAs sharing (l,b) ===================
    __syncthreads();
    if (t == 0) group_barrier(g_barA + (l * Bc + b) * 32, Pc);
    __syncthreads();

    // ===================== Phase 2: softmax + sem (p==0 CTA of each group) =
    if (p == 0) {
        const float bias = s_bias;
        float v[Pc];
        float mxv = -3.4e38f;
        #pragma unroll
        for (int q = 0; q < Pc; q++) {
            float r = __ldcg(g_score + (l * Pc + q) * Bc + b) + bias;
            r = 1.0f / (1.0f + __expf(-r));          // sigmoid
            v[q] = r;
            mxv = fmaxf(mxv, r);
        }
        float sum = 0.0f;
        #pragma unroll
        for (int q = 0; q < Pc; q++) { v[q] = __expf(v[q] - mxv); sum += v[q]; }
        const float inv = 1.0f / sum;

        float4 acc = make_float4(0.f, 0.f, 0.f, 0.f);
        #pragma unroll
        for (int q = 0; q < Pc; q++) {
            const float s = v[q] * inv;
            float4 m = __ldcg(reinterpret_cast<const float4*>(g_mp)
                              + ((size_t)(l * Pc + q) * Bc + b) * W4 + t);
            acc.x += m.x * s; acc.y += m.y * s;
            acc.z += m.z * s; acc.w += m.w * s;
        }
        __stcg(reinterpret_cast<float4*>(g_sem) + ((size_t)l * Bc + b) * W4 + t, acc);
    }

    // ========== Barrier B: sync the 64 CTAs sharing b ======================
    __syncthreads();
    if (t == 0) group_barrier(g_barB + b * 32, Lc * Pc);
    __syncthreads();

    // ===================== Phase 3: out[b, m=lp, w4=t] ======================
    {
        const int m = lp;                    // 0..63
        float4 acc = make_float4(0.f, 0.f, 0.f, 0.f);
        #pragma unroll
        for (int ll = 0; ll < Lc; ll++) {
            const float mk = __ldg(mask + ((size_t)b * Lc + ll) * Mc + m);
            float4 sv = __ldcg(reinterpret_cast<const float4*>(g_sem)
                               + ((size_t)ll * Bc + b) * W4 + t);
            acc.x += mk * sv.x; acc.y += mk * sv.y;
            acc.z += mk * sv.z; acc.w += mk * sv.w;
        }
        reinterpret_cast<float4*>(out)[((size_t)b * Mc + m) * W4 + t] = acc;
    }
}

// ---------------------------------------------------------------------------
extern "C" void kernel_launch(void* const* d_in, const int* in_sizes, int n_in,
                              void* d_out, int out_size)
{
    const float* embeds = (const float*)d_in[0];  // [L,P,S,B,W]
    const float* mask   = (const float*)d_in[1];  // [B,L,M]
    const float* w0     = (const float*)d_in[2];  // [1,W]
    const float* b0     = (const float*)d_in[3];  // [1]
    const float* w1     = (const float*)d_in[4];  // [1,S]
    const float* b1     = (const float*)d_in[5];  // [1]
    float* out          = (float*)d_out;          // [B,M,W]

    fused_kernel<<<NBLK, NTHR>>>(embeds, mask, w0, b0, w1, b1, out);
}